// round 16
// baseline (speedup 1.0000x reference)
#include <cuda_runtime.h>
#include <cuda_fp16.h>
#include <math.h>

typedef unsigned int u32;

#define DOF   7
#define NB    5
#define KDIM  256
#define OUTC  42
#define RPB   64
#define BATCH 65536
#define GRID  (BATCH / RPB)   // 1024
#define TPB   256

// ---- smem layout (bytes). Unpadded 512B rows, XOR-swizzled:
// phys16(r, c) = (c ^ (r & 7)), 16B units; conflict-free for STS/LDSM/cp.async.
#define A_HI   0                    // 64 x 512 = 32768 (x in fp16)
#define B_HI   32768                // 48 x 512 = 24576 -> 57344 (W fp16)
#define BIAS_S 57344                // 48 floats -> 57536
#define SMEM_TOTAL 57600            // x4 CTAs = 230400 <= 233472
// aliases after MMA (A + B tiles dead post-MMA):
#define CS     0                    // 2 x (64*50*4) = 25600
#define EB     25600                // 64*77*4 = 19712 -> 45312 (overlaps B_HI: B
// reads complete before EB writes -- post-MMA __syncthreads -- and B unused after)

// Pre-converted, PRE-SWIZZLED W tile (exact smem byte layout, 48x512B)
__device__ __align__(16) unsigned short g_Bhi[48 * 256];
__device__ __align__(16) float g_bias48[48];

// DMP linear map: y[t] = A[t] . [y0, g, u0..u4, 1]
__constant__ float c_A[11 * 8];

__device__ __forceinline__ u32 sm2u32(const void* p) {
    u32 a; asm("{.reg .u64 t; cvta.to.shared.u64 t,%1; cvt.u32.u64 %0,t;}"
               : "=r"(a) : "l"(p));
    return a;
}
__device__ __forceinline__ void ldsm4(u32 addr, u32& r0, u32& r1, u32& r2, u32& r3) {
    asm volatile("ldmatrix.sync.aligned.m8n8.x4.shared.b16 {%0,%1,%2,%3},[%4];"
                 : "=r"(r0), "=r"(r1), "=r"(r2), "=r"(r3) : "r"(addr));
}
__device__ __forceinline__ void ldsm2(u32 addr, u32& r0, u32& r1) {
    asm volatile("ldmatrix.sync.aligned.m8n8.x2.shared.b16 {%0,%1},[%2];"
                 : "=r"(r0), "=r"(r1) : "r"(addr));
}
__device__ __forceinline__ void mma16816(float* c, const u32* a, u32 b0, u32 b1) {
    asm volatile(
        "mma.sync.aligned.m16n8k16.row.col.f32.f16.f16.f32 "
        "{%0,%1,%2,%3},{%4,%5,%6,%7},{%8,%9},{%0,%1,%2,%3};"
        : "+f"(c[0]), "+f"(c[1]), "+f"(c[2]), "+f"(c[3])
        : "r"(a[0]), "r"(a[1]), "r"(a[2]), "r"(a[3]), "r"(b0), "r"(b1));
}
__device__ __forceinline__ void cp_async16(u32 dst, const void* src) {
    asm volatile("cp.async.cg.shared.global [%0],[%1],16;" :: "r"(dst), "l"(src));
}

// ---------------------------------------------------------------------------
// Prep (once): W -> fp16, stored pre-swizzled:
//   short-off(n, k) = n*256 + (((k>>3) ^ (n&7)) << 3) + (k&7)
// ---------------------------------------------------------------------------
__global__ void prep_w_kernel(const float* __restrict__ W,
                              const float* __restrict__ bias)
{
    int gid = blockIdx.x * 256 + threadIdx.x;   // 48*256 = 12288 threads
    int n = gid >> 8, k = gid & 255;
    unsigned short hi = 0;
    if (n < OUTC) {
        float w = __ldg(W + k * OUTC + n);
        __half h = __float2half_rn(w);
        hi = *(const unsigned short*)&h;
    }
    int off = n * 256 + (((k >> 3) ^ (n & 7)) << 3) + (k & 7);
    g_Bhi[off] = hi;
    if (gid < 48) g_bias48[gid] = (gid < OUTC) ? __ldg(bias + gid) : 0.0f;
}

// ---------------------------------------------------------------------------
__global__ __launch_bounds__(TPB, 4)
void fused_kernel(const float* __restrict__ x, const float* __restrict__ state,
                  float* __restrict__ out)
{
    extern __shared__ __align__(1024) char sm[];
    const u32 smb = sm2u32(sm);
    const int tid = threadIdx.x;
    const int wid = tid >> 5;
    const int lane = tid & 31;

    // ---- B tile via cp.async; bias -> smem ----
    {
        const uint4* sh = (const uint4*)g_Bhi;   // 1536 uint4
        #pragma unroll
        for (int j = 0; j < 6; j++) {
            int i = tid + j * TPB;
            cp_async16(smb + B_HI + 16 * i, sh + i);
        }
        asm volatile("cp.async.commit_group;");
        if (tid < 48) ((float*)(sm + BIAS_S))[tid] = g_bias48[tid];
    }

    // ---- x -> fp16 into swizzled A tile; 4-deep load batches (reg diet) ----
    const float4* xsrc = (const float4*)(x + (size_t)blockIdx.x * RPB * KDIM);
    #pragma unroll
    for (int h = 0; h < 4; h++) {
        float4 v[4];
        #pragma unroll
        for (int j = 0; j < 4; j++)
            v[j] = __ldg(xsrc + tid + (h * 4 + j) * TPB);
        #pragma unroll
        for (int j = 0; j < 4; j++) {
            int idx = tid + (h * 4 + j) * TPB;
            int r = idx >> 6, k4 = idx & 63;
            __half2 h01 = __floats2half2_rn(v[j].x, v[j].y);
            __half2 h23 = __floats2half2_rn(v[j].z, v[j].w);
            u32 off = (u32)(r * 512) + ((((u32)k4 >> 1) ^ ((u32)r & 7u)) << 4)
                    + ((u32)k4 & 1u) * 8u;
            *(uint2*)(sm + A_HI + off) =
                make_uint2(*(const u32*)&h01, *(const u32*)&h23);
        }
    }
    asm volatile("cp.async.wait_group 0;");
    __syncthreads();

    // ---- MMA: 8 warps = 2 m-tiles(32) x 2 k-halves x 2 n-halves(24) ----
    const int mw = wid & 1;            // m-tile: rows mw*32..+31
    const int kh = (wid >> 1) & 1;     // k-half: k16 steps kh*8..+7
    const int nh = wid >> 2;           // n-half: cols nh*24..+23

    float c[2][3][4];
    #pragma unroll
    for (int s2 = 0; s2 < 2; s2++)
        #pragma unroll
        for (int n = 0; n < 3; n++)
            #pragma unroll
            for (int q = 0; q < 4; q++) c[s2][n][q] = 0.0f;

    const u32 sw    = (u32)(lane & 7);           // swizzle constant (row&7)
    const u32 arow  = (u32)((mw * 32 + (lane & 15)) * 512);
    const u32 acolL = (u32)(lane >> 4);
    const u32 brow4 = (u32)((nh * 24 + ((lane & 7) | ((lane >> 4) << 3))) * 512);
    const u32 brow2 = (u32)((nh * 24 + 16 + (lane & 7)) * 512);
    const u32 bcolL = (u32)((lane >> 3) & 1);

    #pragma unroll
    for (int s = 0; s < 8; s++) {
        u32 step = (u32)(kh * 8 + s);                // k16 step 0..15
        u32 ac = ((step * 2u + acolL) ^ sw) << 4;
        u32 bc = ((step * 2u + bcolL) ^ sw) << 4;
        u32 ah[2][4], b0, b1, b2, b3, b4, b5;
        #pragma unroll
        for (int sub = 0; sub < 2; sub++) {
            u32 ad = arow + (u32)sub * (16u * 512u) + ac;
            ldsm4(smb + A_HI + ad, ah[sub][0], ah[sub][1], ah[sub][2], ah[sub][3]);
        }
        ldsm4(smb + B_HI + brow4 + bc, b0, b1, b2, b3);
        ldsm2(smb + B_HI + brow2 + bc, b4, b5);
        #pragma unroll
        for (int sub = 0; sub < 2; sub++) {
            mma16816(c[sub][0], ah[sub], b0, b1);
            mma16816(c[sub][1], ah[sub], b2, b3);
            mma16816(c[sub][2], ah[sub], b4, b5);
        }
    }
    __syncthreads();   // tile reads done before aliases are written

    // ---- stage C partials: cs[kh][row][col], row stride 50 floats ----
    {
        float* cs = (float*)(sm + CS) + kh * (RPB * 50);
        int c0 = nh * 24 + 2 * (lane & 3);
        #pragma unroll
        for (int sub = 0; sub < 2; sub++) {
            int r0 = mw * 32 + sub * 16 + (lane >> 2);
            #pragma unroll
            for (int n = 0; n < 3; n++) {
                int col = c0 + n * 8;
                *(float2*)&cs[r0 * 50 + col]       = make_float2(c[sub][n][0], c[sub][n][1]);
                *(float2*)&cs[(r0 + 8) * 50 + col] = make_float2(c[sub][n][2], c[sub][n][3]);
            }
        }
    }
    __syncthreads();

    // ---- epilogue: linear DMP map, 2 threads per row, per-DOF streaming ----
    if (tid < 2 * RPB) {
        const int row  = tid & 63;
        const int half = tid >> 6;                   // 0: t 0..5, 1: t 6..10
        const float* cs0 = (const float*)(sm + CS) + row * 50;
        const float* cs1 = cs0 + RPB * 50;
        const float* bi  = (const float*)(sm + BIAS_S);
        float* eb = (float*)(sm + EB) + row * 77;
        const float* st = state + ((size_t)(blockIdx.x * RPB + row)) * DOF;
        const int t0 = half ? 6 : 1, t1 = half ? 10 : 5;

        #pragma unroll
        for (int d = 0; d < DOF; d++) {
            float y0 = __ldg(st + d);
            float g  = cs0[d] + cs1[d] + bi[d];
            float ku = g - y0;
            int cw = DOF + 5 * d;
            float w0 = cs0[cw]   + cs1[cw]   + bi[cw];
            float w1 = cs0[cw+1] + cs1[cw+1] + bi[cw+1];
            float w2 = cs0[cw+2] + cs1[cw+2] + bi[cw+2];
            float w3 = cs0[cw+3] + cs1[cw+3] + bi[cw+3];
            float w4 = cs0[cw+4] + cs1[cw+4] + bi[cw+4];
            if (half == 0) eb[d] = y0;               // t = 0
            #pragma unroll
            for (int t = t0; t <= t1; t++) {
                float v = c_A[t*8+2] * w0;
                v = fmaf(c_A[t*8+3], w1, v);
                v = fmaf(c_A[t*8+4], w2, v);
                v = fmaf(c_A[t*8+5], w3, v);
                v = fmaf(c_A[t*8+6], w4, v);
                float yv = fmaf(c_A[t*8+0], y0, c_A[t*8+7]);
                yv = fmaf(c_A[t*8+1], g, yv);
                yv = fmaf(v, ku, yv);
                eb[t * 7 + d] = yv;
            }
        }
    }
    __syncthreads();

    // ---- coalesced output copy: 64*77 floats = 1232 float4 ----
    const float4* s4 = (const float4*)(sm + EB);
    float4* d4 = (float4*)(out + (size_t)blockIdx.x * RPB * 77);
    #pragma unroll
    for (int j = 0; j < 5; j++) {
        int i = tid + j * TPB;
        if (i < (RPB * 77) / 4) d4[i] = s4[i];
    }
}

// ---------------------------------------------------------------------------
// Host: DMP linear map A (8 basis runs of the exact fp32 recursion).
// ---------------------------------------------------------------------------
static float hA[11 * 8];

static void compute_A_host() {
    float c[NB], s2[NB], P[100][NB];
    const float n15 = 11.180339887498949f;     // 5^1.5
    for (int j = 0; j < NB; j++) { c[j] = expf(-0.25f * j); s2[j] = n15 / c[j]; }
    float xv = 1.0f;
    for (int s = 0; s < 100; s++) {
        xv = xv - xv * 0.01f;
        float sum = 0.0f, psi[NB];
        for (int j = 0; j < NB; j++) {
            float d = xv - c[j];
            psi[j] = expf(-0.5f * d * d / s2[j]);
            sum += psi[j];
        }
        for (int j = 0; j < NB; j++) P[s][j] = psi[j] * xv / sum;
    }
    for (int b = 0; b < 8; b++) {              // basis: y0, g, u0..u4, const
        float y = (b == 0) ? 1.0f : 0.0f;
        float gb = (b == 1) ? 1.0f : 0.0f;
        float u[NB];
        for (int j = 0; j < NB; j++) u[j] = (b == 2 + j) ? 1.0f : 0.0f;
        float z = (b == 7) ? 0.05f : 0.0f;
        hA[0 * 8 + b] = y;
        int s = 0;
        for (int tt = 1; tt <= 10; tt++) {
            for (int ss = 0; ss < 10; ss++, s++) {
                float fx = 0.0f;
                for (int j = 0; j < NB; j++) fx += P[s][j] * u[j];
                float dz = 56.25f * (gb - y) - 15.0f * z + fx;
                y = y + z * 0.01f;             // uses old z
                z = z + dz * 0.01f;
            }
            hA[tt * 8 + b] = y;
        }
    }
}

extern "C" void kernel_launch(void* const* d_in, const int* in_sizes, int n_in,
                              void* d_out, int out_size)
{
    const float* x     = (const float*)d_in[0];
    const float* state = (const float*)d_in[1];
    const float* W     = (const float*)d_in[2];
    const float* b     = (const float*)d_in[3];
    float* out = (float*)d_out;

    compute_A_host();
    cudaMemcpyToSymbolAsync(c_A, hA, sizeof(hA), 0, cudaMemcpyHostToDevice);

    prep_w_kernel<<<48, 256>>>(W, b);
    cudaFuncSetAttribute(fused_kernel,
                         cudaFuncAttributeMaxDynamicSharedMemorySize, SMEM_TOTAL);
    fused_kernel<<<GRID, TPB, SMEM_TOTAL>>>(x, state, out);
}

// round 17
// speedup vs baseline: 1.0368x; 1.0368x over previous
#include <cuda_runtime.h>
#include <cuda_fp16.h>
#include <math.h>

typedef unsigned int u32;

#define DOF   7
#define NB    5
#define KDIM  256
#define OUTC  42
#define RPB   64
#define BATCH 65536
#define GRID  (BATCH / RPB)   // 1024
#define TPB   256

// ---- smem layout (bytes). Unpadded 512B rows, XOR-swizzled:
// phys16(r, c) = (c ^ (r & 7)), 16B units; conflict-free for STS/LDSM/cp.async.
#define A_HI   0                    // 64 x 512 = 32768 (x in fp16)
#define B_HI   32768                // 48 x 512 = 24576 -> 57344 (W fp16)
#define SMEM_TOTAL 57344            // 56KB EXACTLY (8KB granule) -> 4 CTAs = 224KB
// aliases after MMA (A + B tiles dead post-MMA):
#define CS     0                    // 2 x (64*50*4) = 25600
#define EB     25600                // 64*77*4 = 19712 -> 45312 (overlaps B_HI: B
// reads complete before EB writes -- post-MMA __syncthreads -- and B unused after)

// Pre-converted, PRE-SWIZZLED W tile (exact smem byte layout, 48x512B)
__device__ __align__(16) unsigned short g_Bhi[48 * 256];
__device__ __align__(16) float g_bias48[48];

// DMP linear map: y[t] = A[t] . [y0, g, u0..u4, 1]
__constant__ float c_A[11 * 8];

__device__ __forceinline__ u32 sm2u32(const void* p) {
    u32 a; asm("{.reg .u64 t; cvta.to.shared.u64 t,%1; cvt.u32.u64 %0,t;}"
               : "=r"(a) : "l"(p));
    return a;
}
__device__ __forceinline__ void ldsm4(u32 addr, u32& r0, u32& r1, u32& r2, u32& r3) {
    asm volatile("ldmatrix.sync.aligned.m8n8.x4.shared.b16 {%0,%1,%2,%3},[%4];"
                 : "=r"(r0), "=r"(r1), "=r"(r2), "=r"(r3) : "r"(addr));
}
__device__ __forceinline__ void ldsm2(u32 addr, u32& r0, u32& r1) {
    asm volatile("ldmatrix.sync.aligned.m8n8.x2.shared.b16 {%0,%1},[%2];"
                 : "=r"(r0), "=r"(r1) : "r"(addr));
}
__device__ __forceinline__ void mma16816(float* c, const u32* a, u32 b0, u32 b1) {
    asm volatile(
        "mma.sync.aligned.m16n8k16.row.col.f32.f16.f16.f32 "
        "{%0,%1,%2,%3},{%4,%5,%6,%7},{%8,%9},{%0,%1,%2,%3};"
        : "+f"(c[0]), "+f"(c[1]), "+f"(c[2]), "+f"(c[3])
        : "r"(a[0]), "r"(a[1]), "r"(a[2]), "r"(a[3]), "r"(b0), "r"(b1));
}
__device__ __forceinline__ void cp_async16(u32 dst, const void* src) {
    asm volatile("cp.async.cg.shared.global [%0],[%1],16;" :: "r"(dst), "l"(src));
}

// ---------------------------------------------------------------------------
// Prep (once): W -> fp16, stored pre-swizzled:
//   short-off(n, k) = n*256 + (((k>>3) ^ (n&7)) << 3) + (k&7)
// ---------------------------------------------------------------------------
__global__ void prep_w_kernel(const float* __restrict__ W,
                              const float* __restrict__ bias)
{
    int gid = blockIdx.x * 256 + threadIdx.x;   // 48*256 = 12288 threads
    int n = gid >> 8, k = gid & 255;
    unsigned short hi = 0;
    if (n < OUTC) {
        float w = __ldg(W + k * OUTC + n);
        __half h = __float2half_rn(w);
        hi = *(const unsigned short*)&h;
    }
    int off = n * 256 + (((k >> 3) ^ (n & 7)) << 3) + (k & 7);
    g_Bhi[off] = hi;
    if (gid < 48) g_bias48[gid] = (gid < OUTC) ? __ldg(bias + gid) : 0.0f;
}

// ---------------------------------------------------------------------------
__global__ __launch_bounds__(TPB, 4)
void fused_kernel(const float* __restrict__ x, const float* __restrict__ state,
                  float* __restrict__ out)
{
    extern __shared__ __align__(1024) char sm[];
    const u32 smb = sm2u32(sm);
    const int tid = threadIdx.x;
    const int wid = tid >> 5;
    const int lane = tid & 31;

    // ---- B tile via cp.async ----
    {
        const uint4* sh = (const uint4*)g_Bhi;   // 1536 uint4
        #pragma unroll
        for (int j = 0; j < 6; j++) {
            int i = tid + j * TPB;
            cp_async16(smb + B_HI + 16 * i, sh + i);
        }
        asm volatile("cp.async.commit_group;");
    }

    // ---- x -> fp16 into swizzled A tile; 4-deep load batches (64-reg diet) ----
    const float4* xsrc = (const float4*)(x + (size_t)blockIdx.x * RPB * KDIM);
    #pragma unroll
    for (int h = 0; h < 4; h++) {
        float4 v[4];
        #pragma unroll
        for (int j = 0; j < 4; j++)
            v[j] = __ldg(xsrc + tid + (h * 4 + j) * TPB);
        #pragma unroll
        for (int j = 0; j < 4; j++) {
            int idx = tid + (h * 4 + j) * TPB;
            int r = idx >> 6, k4 = idx & 63;
            __half2 h01 = __floats2half2_rn(v[j].x, v[j].y);
            __half2 h23 = __floats2half2_rn(v[j].z, v[j].w);
            u32 off = (u32)(r * 512) + ((((u32)k4 >> 1) ^ ((u32)r & 7u)) << 4)
                    + ((u32)k4 & 1u) * 8u;
            *(uint2*)(sm + A_HI + off) =
                make_uint2(*(const u32*)&h01, *(const u32*)&h23);
        }
    }
    asm volatile("cp.async.wait_group 0;");
    __syncthreads();

    // ---- MMA: 8 warps = 2 m-tiles(32) x 2 k-halves x 2 n-halves(24) ----
    const int mw = wid & 1;            // m-tile: rows mw*32..+31
    const int kh = (wid >> 1) & 1;     // k-half: k16 steps kh*8..+7
    const int nh = wid >> 2;           // n-half: cols nh*24..+23

    float c[2][3][4];
    #pragma unroll
    for (int s2 = 0; s2 < 2; s2++)
        #pragma unroll
        for (int n = 0; n < 3; n++)
            #pragma unroll
            for (int q = 0; q < 4; q++) c[s2][n][q] = 0.0f;

    const u32 sw    = (u32)(lane & 7);           // swizzle constant (row&7)
    const u32 arow  = (u32)((mw * 32 + (lane & 15)) * 512);
    const u32 acolL = (u32)(lane >> 4);
    const u32 brow4 = (u32)((nh * 24 + ((lane & 7) | ((lane >> 4) << 3))) * 512);
    const u32 brow2 = (u32)((nh * 24 + 16 + (lane & 7)) * 512);
    const u32 bcolL = (u32)((lane >> 3) & 1);

    #pragma unroll
    for (int s = 0; s < 8; s++) {
        u32 step = (u32)(kh * 8 + s);                // k16 step 0..15
        u32 ac = ((step * 2u + acolL) ^ sw) << 4;
        u32 bc = ((step * 2u + bcolL) ^ sw) << 4;
        u32 ah[2][4], b0, b1, b2, b3, b4, b5;
        #pragma unroll
        for (int sub = 0; sub < 2; sub++) {
            u32 ad = arow + (u32)sub * (16u * 512u) + ac;
            ldsm4(smb + A_HI + ad, ah[sub][0], ah[sub][1], ah[sub][2], ah[sub][3]);
        }
        ldsm4(smb + B_HI + brow4 + bc, b0, b1, b2, b3);
        ldsm2(smb + B_HI + brow2 + bc, b4, b5);
        #pragma unroll
        for (int sub = 0; sub < 2; sub++) {
            mma16816(c[sub][0], ah[sub], b0, b1);
            mma16816(c[sub][1], ah[sub], b2, b3);
            mma16816(c[sub][2], ah[sub], b4, b5);
        }
    }
    __syncthreads();   // tile reads done before aliases are written

    // ---- stage C partials: cs[kh][row][col], row stride 50 floats ----
    {
        float* cs = (float*)(sm + CS) + kh * (RPB * 50);
        int c0 = nh * 24 + 2 * (lane & 3);
        #pragma unroll
        for (int sub = 0; sub < 2; sub++) {
            int r0 = mw * 32 + sub * 16 + (lane >> 2);
            #pragma unroll
            for (int n = 0; n < 3; n++) {
                int col = c0 + n * 8;
                *(float2*)&cs[r0 * 50 + col]       = make_float2(c[sub][n][0], c[sub][n][1]);
                *(float2*)&cs[(r0 + 8) * 50 + col] = make_float2(c[sub][n][2], c[sub][n][3]);
            }
        }
    }
    __syncthreads();

    // ---- epilogue: linear DMP map, 2 threads per row, per-DOF streaming ----
    if (tid < 2 * RPB) {
        const int row  = tid & 63;
        const int half = tid >> 6;                   // 0: t 0..5, 1: t 6..10
        const float* cs0 = (const float*)(sm + CS) + row * 50;
        const float* cs1 = cs0 + RPB * 50;
        float* eb = (float*)(sm + EB) + row * 77;
        const float* st = state + ((size_t)(blockIdx.x * RPB + row)) * DOF;
        const int t0 = half ? 6 : 1, t1 = half ? 10 : 5;

        #pragma unroll
        for (int d = 0; d < DOF; d++) {
            float y0 = __ldg(st + d);
            float g  = cs0[d] + cs1[d] + __ldg(g_bias48 + d);
            float ku = g - y0;
            int cw = DOF + 5 * d;
            float w0 = cs0[cw]   + cs1[cw]   + __ldg(g_bias48 + cw);
            float w1 = cs0[cw+1] + cs1[cw+1] + __ldg(g_bias48 + cw + 1);
            float w2 = cs0[cw+2] + cs1[cw+2] + __ldg(g_bias48 + cw + 2);
            float w3 = cs0[cw+3] + cs1[cw+3] + __ldg(g_bias48 + cw + 3);
            float w4 = cs0[cw+4] + cs1[cw+4] + __ldg(g_bias48 + cw + 4);
            if (half == 0) eb[d] = y0;               // t = 0
            #pragma unroll
            for (int t = t0; t <= t1; t++) {
                float v = c_A[t*8+2] * w0;
                v = fmaf(c_A[t*8+3], w1, v);
                v = fmaf(c_A[t*8+4], w2, v);
                v = fmaf(c_A[t*8+5], w3, v);
                v = fmaf(c_A[t*8+6], w4, v);
                float yv = fmaf(c_A[t*8+0], y0, c_A[t*8+7]);
                yv = fmaf(c_A[t*8+1], g, yv);
                yv = fmaf(v, ku, yv);
                eb[t * 7 + d] = yv;
            }
        }
    }
    __syncthreads();

    // ---- coalesced output copy: 64*77 floats = 1232 float4 ----
    const float4* s4 = (const float4*)(sm + EB);
    float4* d4 = (float4*)(out + (size_t)blockIdx.x * RPB * 77);
    #pragma unroll
    for (int j = 0; j < 5; j++) {
        int i = tid + j * TPB;
        if (i < (RPB * 77) / 4) d4[i] = s4[i];
    }
}

// ---------------------------------------------------------------------------
// Host: DMP linear map A (8 basis runs of the exact fp32 recursion).
// ---------------------------------------------------------------------------
static float hA[11 * 8];

static void compute_A_host() {
    float c[NB], s2[NB], P[100][NB];
    const float n15 = 11.180339887498949f;     // 5^1.5
    for (int j = 0; j < NB; j++) { c[j] = expf(-0.25f * j); s2[j] = n15 / c[j]; }
    float xv = 1.0f;
    for (int s = 0; s < 100; s++) {
        xv = xv - xv * 0.01f;
        float sum = 0.0f, psi[NB];
        for (int j = 0; j < NB; j++) {
            float d = xv - c[j];
            psi[j] = expf(-0.5f * d * d / s2[j]);
            sum += psi[j];
        }
        for (int j = 0; j < NB; j++) P[s][j] = psi[j] * xv / sum;
    }
    for (int b = 0; b < 8; b++) {              // basis: y0, g, u0..u4, const
        float y = (b == 0) ? 1.0f : 0.0f;
        float gb = (b == 1) ? 1.0f : 0.0f;
        float u[NB];
        for (int j = 0; j < NB; j++) u[j] = (b == 2 + j) ? 1.0f : 0.0f;
        float z = (b == 7) ? 0.05f : 0.0f;
        hA[0 * 8 + b] = y;
        int s = 0;
        for (int tt = 1; tt <= 10; tt++) {
            for (int ss = 0; ss < 10; ss++, s++) {
                float fx = 0.0f;
                for (int j = 0; j < NB; j++) fx += P[s][j] * u[j];
                float dz = 56.25f * (gb - y) - 15.0f * z + fx;
                y = y + z * 0.01f;             // uses old z
                z = z + dz * 0.01f;
            }
            hA[tt * 8 + b] = y;
        }
    }
}

extern "C" void kernel_launch(void* const* d_in, const int* in_sizes, int n_in,
                              void* d_out, int out_size)
{
    const float* x     = (const float*)d_in[0];
    const float* state = (const float*)d_in[1];
    const float* W     = (const float*)d_in[2];
    const float* b     = (const float*)d_in[3];
    float* out = (float*)d_out;

    compute_A_host();
    cudaMemcpyToSymbolAsync(c_A, hA, sizeof(hA), 0, cudaMemcpyHostToDevice);

    prep_w_kernel<<<48, 256>>>(W, b);
    cudaFuncSetAttribute(fused_kernel,
                         cudaFuncAttributeMaxDynamicSharedMemorySize, SMEM_TOTAL);
    fused_kernel<<<GRID, TPB, SMEM_TOTAL>>>(x, state, out);
}